// round 1
// baseline (speedup 1.0000x reference)
#include <cuda_runtime.h>

#define D_MODEL 1024
#define NHEAD   16
#define DHEAD   64
#define SEQ     2048
#define MAXB    2

// Scratch (no device allocation allowed) — 4 x 16 MB fp32
__device__ float g_q[MAXB * SEQ * D_MODEL];
__device__ float g_k[MAXB * SEQ * D_MODEL];
__device__ float g_v[MAXB * SEQ * D_MODEL];
__device__ float g_ctx[MAXB * SEQ * D_MODEL];

// ---------------------------------------------------------------------------
// GEMM: Y[M,N] = X[M,K] @ W[N,K]^T + bias[N]   (torch Linear)
// 128x128 block tile, BK=16, 8x8 thread tile, 256 threads.
// ---------------------------------------------------------------------------
#define BM 128
#define BN 128
#define BK 16
#define TM 8
#define TN 8

__global__ __launch_bounds__(256) void gemm_bias_kernel(
    const float* __restrict__ X, const float* __restrict__ W,
    const float* __restrict__ bias, float* __restrict__ Y,
    int M, int N, int K)
{
    __shared__ float As[BK][BM + 4];
    __shared__ float Bs[BK][BN + 4];

    const int tid = threadIdx.x;
    const int m0 = blockIdx.y * BM;
    const int n0 = blockIdx.x * BN;
    const int tm = (tid / 16) * TM;
    const int tn = (tid % 16) * TN;

    const int lr = tid >> 2;        // 0..63
    const int lc = (tid & 3) * 4;   // 0,4,8,12

    float acc[TM][TN];
#pragma unroll
    for (int i = 0; i < TM; i++)
#pragma unroll
        for (int j = 0; j < TN; j++) acc[i][j] = 0.f;

    for (int k0 = 0; k0 < K; k0 += BK) {
#pragma unroll
        for (int i = 0; i < 2; i++) {
            int r = lr + i * 64;
            float4 a = *(const float4*)(X + (size_t)(m0 + r) * K + k0 + lc);
            As[lc + 0][r] = a.x; As[lc + 1][r] = a.y;
            As[lc + 2][r] = a.z; As[lc + 3][r] = a.w;
            float4 b = *(const float4*)(W + (size_t)(n0 + r) * K + k0 + lc);
            Bs[lc + 0][r] = b.x; Bs[lc + 1][r] = b.y;
            Bs[lc + 2][r] = b.z; Bs[lc + 3][r] = b.w;
        }
        __syncthreads();
#pragma unroll
        for (int kk = 0; kk < BK; kk++) {
            float a[TM], b[TN];
#pragma unroll
            for (int i = 0; i < TM; i += 4) {
                float4 t = *(const float4*)&As[kk][tm + i];
                a[i] = t.x; a[i + 1] = t.y; a[i + 2] = t.z; a[i + 3] = t.w;
            }
#pragma unroll
            for (int j = 0; j < TN; j += 4) {
                float4 t = *(const float4*)&Bs[kk][tn + j];
                b[j] = t.x; b[j + 1] = t.y; b[j + 2] = t.z; b[j + 3] = t.w;
            }
#pragma unroll
            for (int i = 0; i < TM; i++)
#pragma unroll
                for (int j = 0; j < TN; j++)
                    acc[i][j] += a[i] * b[j];
        }
        __syncthreads();
    }

#pragma unroll
    for (int i = 0; i < TM; i++) {
        float* yrow = Y + (size_t)(m0 + tm + i) * N + n0 + tn;
#pragma unroll
        for (int j = 0; j < TN; j += 4) {
            float4 bj = *(const float4*)(bias + n0 + tn + j);
            float4 ov;
            ov.x = acc[i][j + 0] + bj.x;
            ov.y = acc[i][j + 1] + bj.y;
            ov.z = acc[i][j + 2] + bj.z;
            ov.w = acc[i][j + 3] + bj.w;
            *(float4*)(yrow + j) = ov;
        }
    }
}

// ---------------------------------------------------------------------------
// Flash attention (causal), fp32, online softmax.
// QT=64 query rows per block, KT=32 keys per iteration, 256 threads.
// grid = (SEQ/QT, NHEAD, B)
// ---------------------------------------------------------------------------
#define QT 64
#define KT 32

__global__ __launch_bounds__(256) void attn_kernel(
    const float* __restrict__ Q, const float* __restrict__ K,
    const float* __restrict__ V, float* __restrict__ Octx)
{
    __shared__ float sQ[QT][DHEAD + 4];
    __shared__ float sK[KT][DHEAD + 4];
    __shared__ float sV[KT][DHEAD + 4];
    __shared__ float sP[QT][KT + 1];
    __shared__ float s_m[QT], s_l[QT], s_corr[QT];

    const int tid = threadIdx.x;
    const int qt = blockIdx.x;
    const int h  = blockIdx.y;
    const int b  = blockIdx.z;

    const size_t base = ((size_t)b * SEQ) * D_MODEL + (size_t)h * DHEAD;

    // Load Q tile (64x64): 1024 float4 -> 4 per thread
#pragma unroll
    for (int i = 0; i < 4; i++) {
        int e = tid + i * 256;
        int r = e >> 4;
        int c = (e & 15) * 4;
        *(float4*)&sQ[r][c] =
            *(const float4*)(Q + base + (size_t)(qt * QT + r) * D_MODEL + c);
    }
    if (tid < QT) { s_m[tid] = -1e30f; s_l[tid] = 0.f; }

    const int r0 = (tid >> 4) * 4;   // query rows r0..r0+3
    const int cq = (tid & 15);       // score cols cq and cq+16
    const int dv = (tid & 15) * 4;   // output dims dv..dv+3

    float o[4][4];
#pragma unroll
    for (int i = 0; i < 4; i++)
#pragma unroll
        for (int j = 0; j < 4; j++) o[i][j] = 0.f;

    const int jmax = 2 * qt + 1;     // causal: keys up to qt*64+63
    const float scale = 0.125f;      // 1/sqrt(64)

    for (int jt = 0; jt <= jmax; jt++) {
        __syncthreads();   // protect sK/sV/sP from previous iteration
        // Load K,V tile (32x64 each): 512 float4 each -> 2 per thread
#pragma unroll
        for (int i = 0; i < 2; i++) {
            int e = tid + i * 256;
            int r = e >> 4;
            int c = (e & 15) * 4;
            size_t g = base + (size_t)(jt * KT + r) * D_MODEL + c;
            *(float4*)&sK[r][c] = *(const float4*)(K + g);
            *(float4*)&sV[r][c] = *(const float4*)(V + g);
        }
        __syncthreads();

        // --- QK^T: each thread computes 4 rows x 2 cols (cq, cq+16) ---
        float s[4][2];
#pragma unroll
        for (int i = 0; i < 4; i++) { s[i][0] = 0.f; s[i][1] = 0.f; }
#pragma unroll
        for (int d4 = 0; d4 < DHEAD; d4 += 4) {
            float4 k0 = *(const float4*)&sK[cq][d4];
            float4 k1 = *(const float4*)&sK[cq + 16][d4];
#pragma unroll
            for (int i = 0; i < 4; i++) {
                float4 qv = *(const float4*)&sQ[r0 + i][d4];
                s[i][0] += qv.x * k0.x + qv.y * k0.y + qv.z * k0.z + qv.w * k0.w;
                s[i][1] += qv.x * k1.x + qv.y * k1.y + qv.z * k1.z + qv.w * k1.w;
            }
        }
        // causal mask + write raw scores
#pragma unroll
        for (int i = 0; i < 4; i++) {
            int qi = qt * QT + r0 + i;
            int k0i = jt * KT + cq;
            int k1i = k0i + 16;
            sP[r0 + i][cq]      = (k0i <= qi) ? s[i][0] * scale : -1e9f;
            sP[r0 + i][cq + 16] = (k1i <= qi) ? s[i][1] * scale : -1e9f;
        }
        __syncthreads();

        // --- online softmax: one thread per query row ---
        if (tid < QT) {
            float m_old = s_m[tid];
            float mt = m_old;
#pragma unroll 8
            for (int c = 0; c < KT; c++) mt = fmaxf(mt, sP[tid][c]);
            float corr = __expf(m_old - mt);
            float lsum = 0.f;
#pragma unroll 8
            for (int c = 0; c < KT; c++) {
                float p = __expf(sP[tid][c] - mt);
                sP[tid][c] = p;
                lsum += p;
            }
            s_m[tid] = mt;
            s_l[tid] = s_l[tid] * corr + lsum;
            s_corr[tid] = corr;
        }
        __syncthreads();

        // --- rescale accumulators + P@V ---
        float c0 = s_corr[r0 + 0], c1 = s_corr[r0 + 1];
        float c2 = s_corr[r0 + 2], c3 = s_corr[r0 + 3];
#pragma unroll
        for (int j = 0; j < 4; j++) {
            o[0][j] *= c0; o[1][j] *= c1; o[2][j] *= c2; o[3][j] *= c3;
        }
#pragma unroll 8
        for (int kk = 0; kk < KT; kk++) {
            float4 vv = *(const float4*)&sV[kk][dv];
            float p0 = sP[r0 + 0][kk];
            float p1 = sP[r0 + 1][kk];
            float p2 = sP[r0 + 2][kk];
            float p3 = sP[r0 + 3][kk];
            o[0][0] += p0 * vv.x; o[0][1] += p0 * vv.y; o[0][2] += p0 * vv.z; o[0][3] += p0 * vv.w;
            o[1][0] += p1 * vv.x; o[1][1] += p1 * vv.y; o[1][2] += p1 * vv.z; o[1][3] += p1 * vv.w;
            o[2][0] += p2 * vv.x; o[2][1] += p2 * vv.y; o[2][2] += p2 * vv.z; o[2][3] += p2 * vv.w;
            o[3][0] += p3 * vv.x; o[3][1] += p3 * vv.y; o[3][2] += p3 * vv.z; o[3][3] += p3 * vv.w;
        }
    }

    // epilogue: normalize and write ctx[b, s, h*64+d]
#pragma unroll
    for (int i = 0; i < 4; i++) {
        float inv = 1.0f / s_l[r0 + i];
        float4 res;
        res.x = o[i][0] * inv; res.y = o[i][1] * inv;
        res.z = o[i][2] * inv; res.w = o[i][3] * inv;
        *(float4*)(Octx + base + (size_t)(qt * QT + r0 + i) * D_MODEL + dv) = res;
    }
}

// ---------------------------------------------------------------------------
extern "C" void kernel_launch(void* const* d_in, const int* in_sizes, int n_in,
                              void* d_out, int out_size)
{
    const float* query = (const float*)d_in[0];
    const float* key   = (const float*)d_in[1];
    const float* value = (const float*)d_in[2];
    // d_in[3] = mask (int32 tril) — causal mask applied analytically in-kernel
    const float* w_q = (const float*)d_in[4];
    const float* b_q = (const float*)d_in[5];
    const float* w_k = (const float*)d_in[6];
    const float* b_k = (const float*)d_in[7];
    const float* w_v = (const float*)d_in[8];
    const float* b_v = (const float*)d_in[9];
    const float* w_o = (const float*)d_in[10];
    const float* b_o = (const float*)d_in[11];
    float* out = (float*)d_out;

    const int M  = in_sizes[0] / D_MODEL;   // B * S
    const int Bn = M / SEQ;                 // batch

    float *q, *k, *v, *ctx;
    cudaGetSymbolAddress((void**)&q,   g_q);
    cudaGetSymbolAddress((void**)&k,   g_k);
    cudaGetSymbolAddress((void**)&v,   g_v);
    cudaGetSymbolAddress((void**)&ctx, g_ctx);

    dim3 ggrid(D_MODEL / BN, M / BM);
    gemm_bias_kernel<<<ggrid, 256>>>(query, w_q, b_q, q, M, D_MODEL, D_MODEL);
    gemm_bias_kernel<<<ggrid, 256>>>(key,   w_k, b_k, k, M, D_MODEL, D_MODEL);
    gemm_bias_kernel<<<ggrid, 256>>>(value, w_v, b_v, v, M, D_MODEL, D_MODEL);

    attn_kernel<<<dim3(SEQ / QT, NHEAD, Bn), 256>>>(q, k, v, ctx);

    gemm_bias_kernel<<<ggrid, 256>>>(ctx, w_o, b_o, out, M, D_MODEL, D_MODEL);
}

// round 4
// speedup vs baseline: 1.4536x; 1.4536x over previous
#include <cuda_runtime.h>
#include <cuda_bf16.h>
#include <cstdint>

#define D_MODEL 1024
#define NHEAD   16
#define DHEAD   64
#define SEQ     2048
#define MAXB    2

// Scratch (no device allocation allowed)
__device__ float g_q[MAXB * SEQ * D_MODEL];
__device__ float g_k[MAXB * SEQ * D_MODEL];
__device__ float g_v[MAXB * SEQ * D_MODEL];
__device__ float g_ctx[MAXB * SEQ * D_MODEL];

// ===========================================================================
// Helpers (baseline PTX only: ldmatrix sm_75+, mma.sync bf16 sm_80+)
// ===========================================================================
__device__ __forceinline__ uint32_t smem_u32(const void* p) {
    uint32_t a;
    asm("{ .reg .u64 t; cvta.to.shared.u64 t, %1; cvt.u32.u64 %0, t; }"
        : "=r"(a) : "l"(p));
    return a;
}

__device__ __forceinline__ void ldsm4(uint32_t* r, uint32_t addr) {
    asm volatile("ldmatrix.sync.aligned.m8n8.x4.shared.b16 {%0,%1,%2,%3}, [%4];"
        : "=r"(r[0]), "=r"(r[1]), "=r"(r[2]), "=r"(r[3]) : "r"(addr));
}

__device__ __forceinline__ void mma16816(float* d, const uint32_t* a, const uint32_t* b) {
    asm volatile(
        "mma.sync.aligned.m16n8k16.row.col.f32.bf16.bf16.f32 "
        "{%0,%1,%2,%3}, {%4,%5,%6,%7}, {%8,%9}, {%0,%1,%2,%3};"
        : "+f"(d[0]), "+f"(d[1]), "+f"(d[2]), "+f"(d[3])
        : "r"(a[0]), "r"(a[1]), "r"(a[2]), "r"(a[3]), "r"(b[0]), "r"(b[1]));
}

__device__ __forceinline__ uint32_t pack_bf(float e, float o) {
    __nv_bfloat162 t = __floats2bfloat162_rn(e, o);   // x=e (low), y=o (high)
    return *reinterpret_cast<uint32_t*>(&t);
}

__device__ __forceinline__ void sts_v2(uint32_t addr, uint32_t v0, uint32_t v1) {
    asm volatile("st.shared.v2.b32 [%0], {%1,%2};" :: "r"(addr), "r"(v0), "r"(v1) : "memory");
}

// ===========================================================================
// GEMM: Y[M,N] = X[M,K] @ W[N,K]^T + bias,  fp32 via bf16 2-term split (HH+HL+LH)
// CTA tile 128x128, 8 warps (warp tile 64x32), BK=32 fp32 per chunk.
// SMEM tile layout per 128-row tile: 128B/row, 16B chunk c16 = 2*(k>>3) + half
// (half: 0=hi, 1=lo), swizzled c16 ^= (row & 7).  Conflict-free for ldmatrix.
// ===========================================================================
#define GBK 32
#define GNCHUNK (D_MODEL / GBK)   // 32

__global__ __launch_bounds__(256, 2) void gemm_mma_kernel(
    const float* __restrict__ X, const float* __restrict__ W,
    const float* __restrict__ bias, float* __restrict__ Y, int M)
{
    __shared__ __align__(1024) uint8_t sA[128 * 128];
    __shared__ __align__(1024) uint8_t sB[128 * 128];
    const uint32_t sAu = smem_u32(sA);
    const uint32_t sBu = smem_u32(sB);

    const int tid  = threadIdx.x;
    const int wid  = tid >> 5;
    const int lane = tid & 31;
    const int m0 = blockIdx.y * 128;
    const int n0 = blockIdx.x * 128;
    const int wm = (wid >> 2) * 64;     // warp M offset (0/64)
    const int wn = (wid & 3) * 32;      // warp N offset (0/32/64/96)

    // Staging mapping: e = i*256+tid; row = e>>3 (0..127), c4 = e&7 (float4 col)
    const int s_row = tid >> 3;         // rows advance by 32 per i
    const int s_c4  = tid & 7;
    const int s_g   = s_c4 >> 1;        // k8 group 0..3
    const int s_sub = (s_c4 & 1) * 8;   // 8B sub-offset within 16B chunk

    float acc[4][4][4];
#pragma unroll
    for (int i = 0; i < 4; i++)
#pragma unroll
        for (int g = 0; g < 4; g++)
#pragma unroll
            for (int r = 0; r < 4; r++) acc[i][g][r] = 0.f;

    for (int c = 0; c < GNCHUNK; c++) {
        const int k0 = c * GBK;
        __syncthreads();   // smem reuse: previous compute done

        // ---- stage A (X rows) and B (W rows): 128x32 fp32 -> hi/lo bf16 ----
#pragma unroll
        for (int i = 0; i < 4; i++) {
            int row = s_row + i * 32;
            int r7 = row & 7;
            uint32_t offH = (uint32_t)(row * 128 + (((2 * s_g)     ^ r7) << 4) + s_sub);
            uint32_t offL = (uint32_t)(row * 128 + (((2 * s_g + 1) ^ r7) << 4) + s_sub);

            float4 a = *(const float4*)(X + (size_t)(m0 + row) * D_MODEL + k0 + s_c4 * 4);
            uint32_t h01 = pack_bf(a.x, a.y);
            uint32_t h23 = pack_bf(a.z, a.w);
            float hx = __uint_as_float(h01 << 16);
            float hy = __uint_as_float(h01 & 0xffff0000u);
            float hz = __uint_as_float(h23 << 16);
            float hw = __uint_as_float(h23 & 0xffff0000u);
            uint32_t l01 = pack_bf(a.x - hx, a.y - hy);
            uint32_t l23 = pack_bf(a.z - hz, a.w - hw);
            sts_v2(sAu + offH, h01, h23);
            sts_v2(sAu + offL, l01, l23);

            float4 b = *(const float4*)(W + (size_t)(n0 + row) * D_MODEL + k0 + s_c4 * 4);
            h01 = pack_bf(b.x, b.y);
            h23 = pack_bf(b.z, b.w);
            hx = __uint_as_float(h01 << 16);
            hy = __uint_as_float(h01 & 0xffff0000u);
            hz = __uint_as_float(h23 << 16);
            hw = __uint_as_float(h23 & 0xffff0000u);
            l01 = pack_bf(b.x - hx, b.y - hy);
            l23 = pack_bf(b.z - hz, b.w - hw);
            sts_v2(sBu + offH, h01, h23);
            sts_v2(sBu + offL, l01, l23);
        }
        __syncthreads();

        // ---- compute: 2 k16 steps, 4 m16 x 4 n8 x {HH,HL,LH} ----
#pragma unroll
        for (int ks = 0; ks < 2; ks++) {
            uint32_t aH[4][4], aL[4][4], bH[4][2], bL[4][2];

            {
                int rA = wm + (lane & 15);
                int cHi = 4 * ks + 2 * ((lane >> 4) & 1);
                int r7 = rA & 7;
                uint32_t base = sAu + (uint32_t)rA * 128;
                uint32_t pH = (uint32_t)((cHi ^ r7) << 4);
                uint32_t pL = (uint32_t)(((cHi + 1) ^ r7) << 4);
#pragma unroll
                for (int i = 0; i < 4; i++) {
                    ldsm4(aH[i], base + i * 2048 + pH);
                    ldsm4(aL[i], base + i * 2048 + pL);
                }
            }
            {
                int rBb = wn + (lane & 7) + ((lane >> 4) & 1) * 8;
                int cHi = 4 * ks + 2 * ((lane >> 3) & 1);
#pragma unroll
                for (int j = 0; j < 2; j++) {
                    int rB = rBb + j * 16;
                    int r7 = rB & 7;
                    uint32_t base = sBu + (uint32_t)rB * 128;
                    uint32_t t[4];
                    ldsm4(t, base + (uint32_t)((cHi ^ r7) << 4));
                    bH[2 * j][0] = t[0]; bH[2 * j][1] = t[1];
                    bH[2 * j + 1][0] = t[2]; bH[2 * j + 1][1] = t[3];
                    ldsm4(t, base + (uint32_t)(((cHi + 1) ^ r7) << 4));
                    bL[2 * j][0] = t[0]; bL[2 * j][1] = t[1];
                    bL[2 * j + 1][0] = t[2]; bL[2 * j + 1][1] = t[3];
                }
            }
#pragma unroll
            for (int i = 0; i < 4; i++)
#pragma unroll
                for (int g = 0; g < 4; g++) {
                    mma16816(acc[i][g], aH[i], bH[g]);
                    mma16816(acc[i][g], aH[i], bL[g]);
                    mma16816(acc[i][g], aL[i], bH[g]);
                }
        }
    }

    // ---- epilogue: bias add + store (fragment layout direct to global) ----
#pragma unroll
    for (int i = 0; i < 4; i++) {
        int row = m0 + wm + i * 16 + (lane >> 2);
#pragma unroll
        for (int g = 0; g < 4; g++) {
            int col = n0 + wn + g * 8 + (lane & 3) * 2;
            float2 b2 = *(const float2*)(bias + col);
            float2 o0, o1;
            o0.x = acc[i][g][0] + b2.x; o0.y = acc[i][g][1] + b2.y;
            o1.x = acc[i][g][2] + b2.x; o1.y = acc[i][g][3] + b2.y;
            *(float2*)(Y + (size_t)row * D_MODEL + col) = o0;
            *(float2*)(Y + (size_t)(row + 8) * D_MODEL + col) = o1;
        }
    }
}

// ===========================================================================
// Flash attention (causal), fp32, online softmax (unchanged from R1).
// ===========================================================================
#define QT 64
#define KT 32

__global__ __launch_bounds__(256) void attn_kernel(
    const float* __restrict__ Q, const float* __restrict__ K,
    const float* __restrict__ V, float* __restrict__ Octx)
{
    __shared__ float sQ[QT][DHEAD + 4];
    __shared__ float sK[KT][DHEAD + 4];
    __shared__ float sV[KT][DHEAD + 4];
    __shared__ float sP[QT][KT + 1];
    __shared__ float s_m[QT], s_l[QT], s_corr[QT];

    const int tid = threadIdx.x;
    const int qt = blockIdx.x;
    const int h  = blockIdx.y;
    const int b  = blockIdx.z;

    const size_t base = ((size_t)b * SEQ) * D_MODEL + (size_t)h * DHEAD;

#pragma unroll
    for (int i = 0; i < 4; i++) {
        int e = tid + i * 256;
        int r = e >> 4;
        int c = (e & 15) * 4;
        *(float4*)&sQ[r][c] =
            *(const float4*)(Q + base + (size_t)(qt * QT + r) * D_MODEL + c);
    }
    if (tid < QT) { s_m[tid] = -1e30f; s_l[tid] = 0.f; }

    const int r0 = (tid >> 4) * 4;
    const int cq = (tid & 15);
    const int dv = (tid & 15) * 4;

    float o[4][4];
#pragma unroll
    for (int i = 0; i < 4; i++)
#pragma unroll
        for (int j = 0; j < 4; j++) o[i][j] = 0.f;

    const int jmax = 2 * qt + 1;
    const float scale = 0.125f;

    for (int jt = 0; jt <= jmax; jt++) {
        __syncthreads();
#pragma unroll
        for (int i = 0; i < 2; i++) {
            int e = tid + i * 256;
            int r = e >> 4;
            int c = (e & 15) * 4;
            size_t g = base + (size_t)(jt * KT + r) * D_MODEL + c;
            *(float4*)&sK[r][c] = *(const float4*)(K + g);
            *(float4*)&sV[r][c] = *(const float4*)(V + g);
        }
        __syncthreads();

        float s[4][2];
#pragma unroll
        for (int i = 0; i < 4; i++) { s[i][0] = 0.f; s[i][1] = 0.f; }
#pragma unroll
        for (int d4 = 0; d4 < DHEAD; d4 += 4) {
            float4 k0 = *(const float4*)&sK[cq][d4];
            float4 k1 = *(const float4*)&sK[cq + 16][d4];
#pragma unroll
            for (int i = 0; i < 4; i++) {
                float4 qv = *(const float4*)&sQ[r0 + i][d4];
                s[i][0] += qv.x * k0.x + qv.y * k0.y + qv.z * k0.z + qv.w * k0.w;
                s[i][1] += qv.x * k1.x + qv.y * k1.y + qv.z * k1.z + qv.w * k1.w;
            }
        }
#pragma unroll
        for (int i = 0; i < 4; i++) {
            int qi = qt * QT + r0 + i;
            int k0i = jt * KT + cq;
            int k1i = k0i + 16;
            sP[r0 + i][cq]      = (k0i <= qi) ? s[i][0] * scale : -1e9f;
            sP[r0 + i][cq + 16] = (k1i <= qi) ? s[i][1] * scale : -1e9f;
        }
        __syncthreads();

        if (tid < QT) {
            float m_old = s_m[tid];
            float mt = m_old;
#pragma unroll 8
            for (int c = 0; c < KT; c++) mt = fmaxf(mt, sP[tid][c]);
            float corr = __expf(m_old - mt);
            float lsum = 0.f;
#pragma unroll 8
            for (int c = 0; c < KT; c++) {
                float p = __expf(sP[tid][c] - mt);
                sP[tid][c] = p;
                lsum += p;
            }
            s_m[tid] = mt;
            s_l[tid] = s_l[tid] * corr + lsum;
            s_corr[tid] = corr;
        }
        __syncthreads();

        float c0 = s_corr[r0 + 0], c1 = s_corr[r0 + 1];
        float c2 = s_corr[r0 + 2], c3 = s_corr[r0 + 3];
#pragma unroll
        for (int j = 0; j < 4; j++) {
            o[0][j] *= c0; o[1][j] *= c1; o[2][j] *= c2; o[3][j] *= c3;
        }
#pragma unroll 8
        for (int kk = 0; kk < KT; kk++) {
            float4 vv = *(const float4*)&sV[kk][dv];
            float p0 = sP[r0 + 0][kk];
            float p1 = sP[r0 + 1][kk];
            float p2 = sP[r0 + 2][kk];
            float p3 = sP[r0 + 3][kk];
            o[0][0] += p0 * vv.x; o[0][1] += p0 * vv.y; o[0][2] += p0 * vv.z; o[0][3] += p0 * vv.w;
            o[1][0] += p1 * vv.x; o[1][1] += p1 * vv.y; o[1][2] += p1 * vv.z; o[1][3] += p1 * vv.w;
            o[2][0] += p2 * vv.x; o[2][1] += p2 * vv.y; o[2][2] += p2 * vv.z; o[2][3] += p2 * vv.w;
            o[3][0] += p3 * vv.x; o[3][1] += p3 * vv.y; o[3][2] += p3 * vv.z; o[3][3] += p3 * vv.w;
        }
    }

#pragma unroll
    for (int i = 0; i < 4; i++) {
        float inv = 1.0f / s_l[r0 + i];
        float4 res;
        res.x = o[i][0] * inv; res.y = o[i][1] * inv;
        res.z = o[i][2] * inv; res.w = o[i][3] * inv;
        *(float4*)(Octx + base + (size_t)(qt * QT + r0 + i) * D_MODEL + dv) = res;
    }
}

// ===========================================================================
extern "C" void kernel_launch(void* const* d_in, const int* in_sizes, int n_in,
                              void* d_out, int out_size)
{
    const float* query = (const float*)d_in[0];
    const float* key   = (const float*)d_in[1];
    const float* value = (const float*)d_in[2];
    // d_in[3] = mask (int32 tril) — causal mask applied analytically in-kernel
    const float* w_q = (const float*)d_in[4];
    const float* b_q = (const float*)d_in[5];
    const float* w_k = (const float*)d_in[6];
    const float* b_k = (const float*)d_in[7];
    const float* w_v = (const float*)d_in[8];
    const float* b_v = (const float*)d_in[9];
    const float* w_o = (const float*)d_in[10];
    const float* b_o = (const float*)d_in[11];
    float* out = (float*)d_out;

    const int M  = in_sizes[0] / D_MODEL;   // B * S
    const int Bn = M / SEQ;

    float *q, *k, *v, *ctx;
    cudaGetSymbolAddress((void**)&q,   g_q);
    cudaGetSymbolAddress((void**)&k,   g_k);
    cudaGetSymbolAddress((void**)&v,   g_v);
    cudaGetSymbolAddress((void**)&ctx, g_ctx);

    dim3 ggrid(D_MODEL / 128, M / 128);
    gemm_mma_kernel<<<ggrid, 256>>>(query, w_q, b_q, q, M);
    gemm_mma_kernel<<<ggrid, 256>>>(key,   w_k, b_k, k, M);
    gemm_mma_kernel<<<ggrid, 256>>>(value, w_v, b_v, v, M);

    attn_kernel<<<dim3(SEQ / QT, NHEAD, Bn), 256>>>(q, k, v, ctx);

    gemm_mma_kernel<<<ggrid, 256>>>(ctx, w_o, b_o, out, M);
}

// round 5
// speedup vs baseline: 2.7742x; 1.9086x over previous
#include <cuda_runtime.h>
#include <cuda_bf16.h>
#include <cstdint>

#define D_MODEL 1024
#define NHEAD   16
#define DHEAD   64
#define SEQ     2048
#define MAXB    2

// Scratch (no device allocation allowed)
__device__ float g_q[MAXB * SEQ * D_MODEL];
__device__ float g_k[MAXB * SEQ * D_MODEL];
__device__ float g_v[MAXB * SEQ * D_MODEL];
__device__ float g_ctx[MAXB * SEQ * D_MODEL];

// ===========================================================================
// Helpers (baseline PTX only: ldmatrix sm_75+, mma.sync bf16 sm_80+)
// ===========================================================================
__device__ __forceinline__ uint32_t smem_u32(const void* p) {
    uint32_t a;
    asm("{ .reg .u64 t; cvta.to.shared.u64 t, %1; cvt.u32.u64 %0, t; }"
        : "=r"(a) : "l"(p));
    return a;
}

__device__ __forceinline__ void ldsm4(uint32_t* r, uint32_t addr) {
    asm volatile("ldmatrix.sync.aligned.m8n8.x4.shared.b16 {%0,%1,%2,%3}, [%4];"
        : "=r"(r[0]), "=r"(r[1]), "=r"(r[2]), "=r"(r[3]) : "r"(addr));
}

__device__ __forceinline__ void ldsm4t(uint32_t* r, uint32_t addr) {
    asm volatile("ldmatrix.sync.aligned.m8n8.x4.trans.shared.b16 {%0,%1,%2,%3}, [%4];"
        : "=r"(r[0]), "=r"(r[1]), "=r"(r[2]), "=r"(r[3]) : "r"(addr));
}

__device__ __forceinline__ void mma16816(float* d, const uint32_t* a, const uint32_t* b) {
    asm volatile(
        "mma.sync.aligned.m16n8k16.row.col.f32.bf16.bf16.f32 "
        "{%0,%1,%2,%3}, {%4,%5,%6,%7}, {%8,%9}, {%0,%1,%2,%3};"
        : "+f"(d[0]), "+f"(d[1]), "+f"(d[2]), "+f"(d[3])
        : "r"(a[0]), "r"(a[1]), "r"(a[2]), "r"(a[3]), "r"(b[0]), "r"(b[1]));
}

__device__ __forceinline__ uint32_t pack_bf(float e, float o) {
    __nv_bfloat162 t = __floats2bfloat162_rn(e, o);   // x=e (low), y=o (high)
    return *reinterpret_cast<uint32_t*>(&t);
}

__device__ __forceinline__ void sts_v2(uint32_t addr, uint32_t v0, uint32_t v1) {
    asm volatile("st.shared.v2.b32 [%0], {%1,%2};" :: "r"(addr), "r"(v0), "r"(v1) : "memory");
}

// fp32 -> (hi, lo) bf16x2 pair
__device__ __forceinline__ void split2(float a, float b, uint32_t& hi, uint32_t& lo) {
    hi = pack_bf(a, b);
    float ha = __uint_as_float(hi << 16);
    float hb = __uint_as_float(hi & 0xffff0000u);
    lo = pack_bf(a - ha, b - hb);
}

// ===========================================================================
// GEMM: Y[M,N] = X[M,K] @ W[N,K]^T + bias,  fp32 via bf16 2-term split (HH+HL+LH)
// CTA tile 128x128, 8 warps (warp tile 64x32), BK=32 fp32 per chunk.
// ===========================================================================
#define GBK 32
#define GNCHUNK (D_MODEL / GBK)   // 32

__global__ __launch_bounds__(256, 2) void gemm_mma_kernel(
    const float* __restrict__ X, const float* __restrict__ W,
    const float* __restrict__ bias, float* __restrict__ Y, int M)
{
    __shared__ __align__(1024) uint8_t sA[128 * 128];
    __shared__ __align__(1024) uint8_t sB[128 * 128];
    const uint32_t sAu = smem_u32(sA);
    const uint32_t sBu = smem_u32(sB);

    const int tid  = threadIdx.x;
    const int wid  = tid >> 5;
    const int lane = tid & 31;
    const int m0 = blockIdx.y * 128;
    const int n0 = blockIdx.x * 128;
    const int wm = (wid >> 2) * 64;
    const int wn = (wid & 3) * 32;

    const int s_row = tid >> 3;
    const int s_c4  = tid & 7;
    const int s_g   = s_c4 >> 1;
    const int s_sub = (s_c4 & 1) * 8;

    float acc[4][4][4];
#pragma unroll
    for (int i = 0; i < 4; i++)
#pragma unroll
        for (int g = 0; g < 4; g++)
#pragma unroll
            for (int r = 0; r < 4; r++) acc[i][g][r] = 0.f;

    for (int c = 0; c < GNCHUNK; c++) {
        const int k0 = c * GBK;
        __syncthreads();

#pragma unroll
        for (int i = 0; i < 4; i++) {
            int row = s_row + i * 32;
            int r7 = row & 7;
            uint32_t offH = (uint32_t)(row * 128 + (((2 * s_g)     ^ r7) << 4) + s_sub);
            uint32_t offL = (uint32_t)(row * 128 + (((2 * s_g + 1) ^ r7) << 4) + s_sub);

            float4 a = *(const float4*)(X + (size_t)(m0 + row) * D_MODEL + k0 + s_c4 * 4);
            uint32_t h01, l01, h23, l23;
            split2(a.x, a.y, h01, l01);
            split2(a.z, a.w, h23, l23);
            sts_v2(sAu + offH, h01, h23);
            sts_v2(sAu + offL, l01, l23);

            float4 b = *(const float4*)(W + (size_t)(n0 + row) * D_MODEL + k0 + s_c4 * 4);
            split2(b.x, b.y, h01, l01);
            split2(b.z, b.w, h23, l23);
            sts_v2(sBu + offH, h01, h23);
            sts_v2(sBu + offL, l01, l23);
        }
        __syncthreads();

#pragma unroll
        for (int ks = 0; ks < 2; ks++) {
            uint32_t aH[4][4], aL[4][4], bH[4][2], bL[4][2];
            {
                int rA = wm + (lane & 15);
                int cHi = 4 * ks + 2 * ((lane >> 4) & 1);
                int r7 = rA & 7;
                uint32_t base = sAu + (uint32_t)rA * 128;
                uint32_t pH = (uint32_t)((cHi ^ r7) << 4);
                uint32_t pL = (uint32_t)(((cHi + 1) ^ r7) << 4);
#pragma unroll
                for (int i = 0; i < 4; i++) {
                    ldsm4(aH[i], base + i * 2048 + pH);
                    ldsm4(aL[i], base + i * 2048 + pL);
                }
            }
            {
                int rBb = wn + (lane & 7) + ((lane >> 4) & 1) * 8;
                int cHi = 4 * ks + 2 * ((lane >> 3) & 1);
#pragma unroll
                for (int j = 0; j < 2; j++) {
                    int rB = rBb + j * 16;
                    int r7 = rB & 7;
                    uint32_t base = sBu + (uint32_t)rB * 128;
                    uint32_t t[4];
                    ldsm4(t, base + (uint32_t)((cHi ^ r7) << 4));
                    bH[2 * j][0] = t[0]; bH[2 * j][1] = t[1];
                    bH[2 * j + 1][0] = t[2]; bH[2 * j + 1][1] = t[3];
                    ldsm4(t, base + (uint32_t)(((cHi + 1) ^ r7) << 4));
                    bL[2 * j][0] = t[0]; bL[2 * j][1] = t[1];
                    bL[2 * j + 1][0] = t[2]; bL[2 * j + 1][1] = t[3];
                }
            }
#pragma unroll
            for (int i = 0; i < 4; i++)
#pragma unroll
                for (int g = 0; g < 4; g++) {
                    mma16816(acc[i][g], aH[i], bH[g]);
                    mma16816(acc[i][g], aH[i], bL[g]);
                    mma16816(acc[i][g], aL[i], bH[g]);
                }
        }
    }

#pragma unroll
    for (int i = 0; i < 4; i++) {
        int row = m0 + wm + i * 16 + (lane >> 2);
#pragma unroll
        for (int g = 0; g < 4; g++) {
            int col = n0 + wn + g * 8 + (lane & 3) * 2;
            float2 b2 = *(const float2*)(bias + col);
            float2 o0, o1;
            o0.x = acc[i][g][0] + b2.x; o0.y = acc[i][g][1] + b2.y;
            o1.x = acc[i][g][2] + b2.x; o1.y = acc[i][g][3] + b2.y;
            *(float2*)(Y + (size_t)row * D_MODEL + col) = o0;
            *(float2*)(Y + (size_t)(row + 8) * D_MODEL + col) = o1;
        }
    }
}

// ===========================================================================
// Flash attention (causal) on mma.sync bf16 with 2-term split.
// CTA: 128 q-rows, 8 warps (warp = m16 x all 64 keys x all 64 dims).
// Key tiles of 64; online softmax fully in registers (FA2 style).
// SMEM tiles (hi/lo separate): row*128B + ((c16 ^ (row&7))<<4) swizzle.
// ===========================================================================
#define AQ 128
#define AK 64
#define ATTN_SMEM 65536   // Qh/Ql 16K each, Kh/Kl 8K each, Vh/Vl 8K each

__global__ __launch_bounds__(256) void attn_mma_kernel(
    const float* __restrict__ Q, const float* __restrict__ K,
    const float* __restrict__ V, float* __restrict__ Octx)
{
    extern __shared__ uint8_t dsm[];
    const uint32_t sQh = smem_u32(dsm);
    const uint32_t sQl = sQh + 16384;
    const uint32_t sKh = sQh + 32768;
    const uint32_t sKl = sQh + 40960;
    const uint32_t sVh = sQh + 49152;
    const uint32_t sVl = sQh + 57344;

    const int tid  = threadIdx.x;
    const int wid  = tid >> 5;
    const int lane = tid & 31;
    const int qt = blockIdx.x;
    const int h  = blockIdx.y;
    const int b  = blockIdx.z;
    const size_t base = ((size_t)b * SEQ) * D_MODEL + (size_t)h * DHEAD;

    // staging mapping (64 dims = 16 float4 per row)
    const int srow = tid >> 4;      // 0..15
    const int c4   = tid & 15;
    const int c16s = c4 >> 1;
    const int sub  = (c4 & 1) * 8;

    // ---- stage Q once: 128 x 64 fp32 -> hi/lo swizzled bf16 ----
#pragma unroll
    for (int i = 0; i < 8; i++) {
        int row = i * 16 + srow;
        uint32_t off = (uint32_t)(row * 128 + ((c16s ^ (row & 7)) << 4) + sub);
        float4 a = *(const float4*)(Q + base + (size_t)(qt * AQ + row) * D_MODEL + c4 * 4);
        uint32_t h0, l0r, h1, l1r;
        split2(a.x, a.y, h0, l0r);
        split2(a.z, a.w, h1, l1r);
        sts_v2(sQh + off, h0, h1);
        sts_v2(sQl + off, l0r, l1r);
    }

    uint32_t qh[4][4], ql[4][4];
    float O[8][4];
#pragma unroll
    for (int g = 0; g < 8; g++)
#pragma unroll
        for (int r = 0; r < 4; r++) O[g][r] = 0.f;
    float m0 = -1e30f, m1 = -1e30f, l0 = 0.f, l1 = 0.f;

    const int nkt   = 2 * qt + 2;
    const int wrow0 = qt * AQ + wid * 16;     // warp's first global q-row
    const float scale = 0.125f;               // 1/sqrt(64)

    for (int jt = 0; jt < nkt; jt++) {
        __syncthreads();   // prior compute done (iter0: Q stores done)
        // ---- stage K, V tile: 64 x 64 fp32 each ----
#pragma unroll
        for (int i = 0; i < 4; i++) {
            int row = i * 16 + srow;
            uint32_t off = (uint32_t)(row * 128 + ((c16s ^ (row & 7)) << 4) + sub);
            size_t g = base + (size_t)(jt * AK + row) * D_MODEL + c4 * 4;
            float4 kk = *(const float4*)(K + g);
            uint32_t h0, lo0, h1, lo1;
            split2(kk.x, kk.y, h0, lo0);
            split2(kk.z, kk.w, h1, lo1);
            sts_v2(sKh + off, h0, h1);
            sts_v2(sKl + off, lo0, lo1);
            float4 vv = *(const float4*)(V + g);
            split2(vv.x, vv.y, h0, lo0);
            split2(vv.z, vv.w, h1, lo1);
            sts_v2(sVh + off, h0, h1);
            sts_v2(sVl + off, lo0, lo1);
        }
        __syncthreads();

        if (jt == 0) {   // load persistent Q fragments
#pragma unroll
            for (int ks = 0; ks < 4; ks++) {
                int row = (wid << 4) + (lane & 15);
                int c16 = 2 * ks + (lane >> 4);
                uint32_t addr = (uint32_t)(row * 128 + ((c16 ^ (row & 7)) << 4));
                ldsm4(qh[ks], sQh + addr);
                ldsm4(ql[ks], sQl + addr);
            }
        }

        if (wrow0 + 15 < jt * AK) continue;   // warp tile fully masked (warp-uniform)

        // ---- S = Q @ K^T  (8 n8-tiles of keys) ----
        float S[8][4];
#pragma unroll
        for (int g = 0; g < 8; g++)
#pragma unroll
            for (int r = 0; r < 4; r++) S[g][r] = 0.f;

#pragma unroll
        for (int ks = 0; ks < 4; ks++) {
            uint32_t kh[4][4], kl[4][4];
#pragma unroll
            for (int g2 = 0; g2 < 4; g2++) {
                int key = g2 * 16 + (lane & 7) + ((lane >> 4) & 1) * 8;
                int c16 = 2 * ks + ((lane >> 3) & 1);
                uint32_t addr = (uint32_t)(key * 128 + ((c16 ^ (key & 7)) << 4));
                ldsm4(kh[g2], sKh + addr);
                ldsm4(kl[g2], sKl + addr);
            }
#pragma unroll
            for (int g2 = 0; g2 < 4; g2++) {
                mma16816(S[2 * g2],     qh[ks], &kh[g2][0]);
                mma16816(S[2 * g2],     qh[ks], &kl[g2][0]);
                mma16816(S[2 * g2],     ql[ks], &kh[g2][0]);
                mma16816(S[2 * g2 + 1], qh[ks], &kh[g2][2]);
                mma16816(S[2 * g2 + 1], qh[ks], &kl[g2][2]);
                mma16816(S[2 * g2 + 1], ql[ks], &kh[g2][2]);
            }
        }

        // ---- scale + causal mask ----
        const int r0g  = wrow0 + (lane >> 2);
        const bool domask = (jt * AK + 63) > wrow0;
        if (domask) {
            const int key0 = jt * AK + 2 * (lane & 3);
#pragma unroll
            for (int g = 0; g < 8; g++) {
                int kk = key0 + 8 * g;
                S[g][0] = (kk     <= r0g)     ? S[g][0] * scale : -1e30f;
                S[g][1] = (kk + 1 <= r0g)     ? S[g][1] * scale : -1e30f;
                S[g][2] = (kk     <= r0g + 8) ? S[g][2] * scale : -1e30f;
                S[g][3] = (kk + 1 <= r0g + 8) ? S[g][3] * scale : -1e30f;
            }
        } else {
#pragma unroll
            for (int g = 0; g < 8; g++) {
                S[g][0] *= scale; S[g][1] *= scale;
                S[g][2] *= scale; S[g][3] *= scale;
            }
        }

        // ---- online softmax (rows r0g, r0g+8) ----
        float mx0 = S[0][0], mx1 = S[0][2];
#pragma unroll
        for (int g = 0; g < 8; g++) {
            mx0 = fmaxf(mx0, fmaxf(S[g][0], S[g][1]));
            mx1 = fmaxf(mx1, fmaxf(S[g][2], S[g][3]));
        }
        mx0 = fmaxf(mx0, __shfl_xor_sync(0xffffffffu, mx0, 1));
        mx0 = fmaxf(mx0, __shfl_xor_sync(0xffffffffu, mx0, 2));
        mx1 = fmaxf(mx1, __shfl_xor_sync(0xffffffffu, mx1, 1));
        mx1 = fmaxf(mx1, __shfl_xor_sync(0xffffffffu, mx1, 2));
        float mn0 = fmaxf(m0, mx0), mn1 = fmaxf(m1, mx1);
        float corr0 = __expf(m0 - mn0), corr1 = __expf(m1 - mn1);
        m0 = mn0; m1 = mn1;

        float la0 = 0.f, la1 = 0.f;
        uint32_t ph[4][4], pl[4][4];    // P A-fragments (hi/lo) per k16 step
#pragma unroll
        for (int j = 0; j < 4; j++) {
            float p00 = __expf(S[2 * j][0] - mn0);
            float p01 = __expf(S[2 * j][1] - mn0);
            float p10 = __expf(S[2 * j][2] - mn1);
            float p11 = __expf(S[2 * j][3] - mn1);
            float p20 = __expf(S[2 * j + 1][0] - mn0);
            float p21 = __expf(S[2 * j + 1][1] - mn0);
            float p30 = __expf(S[2 * j + 1][2] - mn1);
            float p31 = __expf(S[2 * j + 1][3] - mn1);
            la0 += p00 + p01 + p20 + p21;
            la1 += p10 + p11 + p30 + p31;
            split2(p00, p01, ph[j][0], pl[j][0]);
            split2(p10, p11, ph[j][1], pl[j][1]);
            split2(p20, p21, ph[j][2], pl[j][2]);
            split2(p30, p31, ph[j][3], pl[j][3]);
        }
        l0 = l0 * corr0 + la0;
        l1 = l1 * corr1 + la1;
#pragma unroll
        for (int g = 0; g < 8; g++) {
            O[g][0] *= corr0; O[g][1] *= corr0;
            O[g][2] *= corr1; O[g][3] *= corr1;
        }

        // ---- O += P @ V  (8 n8-tiles of dims) ----
#pragma unroll
        for (int ks = 0; ks < 4; ks++) {
            uint32_t vh[4][4], vl[4][4];
#pragma unroll
            for (int d2 = 0; d2 < 4; d2++) {
                int row = 16 * ks + (lane & 7) + ((lane >> 3) & 1) * 8;
                int c16 = 2 * d2 + ((lane >> 4) & 1);
                uint32_t addr = (uint32_t)(row * 128 + ((c16 ^ (row & 7)) << 4));
                ldsm4t(vh[d2], sVh + addr);
                ldsm4t(vl[d2], sVl + addr);
            }
#pragma unroll
            for (int d2 = 0; d2 < 4; d2++) {
                mma16816(O[2 * d2],     ph[ks], &vh[d2][0]);
                mma16816(O[2 * d2],     ph[ks], &vl[d2][0]);
                mma16816(O[2 * d2],     pl[ks], &vh[d2][0]);
                mma16816(O[2 * d2 + 1], ph[ks], &vh[d2][2]);
                mma16816(O[2 * d2 + 1], ph[ks], &vl[d2][2]);
                mma16816(O[2 * d2 + 1], pl[ks], &vh[d2][2]);
            }
        }
    }

    // ---- epilogue: quad-reduce l, normalize, store ----
    l0 += __shfl_xor_sync(0xffffffffu, l0, 1);
    l0 += __shfl_xor_sync(0xffffffffu, l0, 2);
    l1 += __shfl_xor_sync(0xffffffffu, l1, 1);
    l1 += __shfl_xor_sync(0xffffffffu, l1, 2);
    float inv0 = 1.f / l0, inv1 = 1.f / l1;
    const int r0g = wrow0 + (lane >> 2);
#pragma unroll
    for (int g = 0; g < 8; g++) {
        int dim = 8 * g + 2 * (lane & 3);
        float2 o0, o1;
        o0.x = O[g][0] * inv0; o0.y = O[g][1] * inv0;
        o1.x = O[g][2] * inv1; o1.y = O[g][3] * inv1;
        *(float2*)(Octx + base + (size_t)r0g * D_MODEL + dim) = o0;
        *(float2*)(Octx + base + (size_t)(r0g + 8) * D_MODEL + dim) = o1;
    }
}

// ===========================================================================
extern "C" void kernel_launch(void* const* d_in, const int* in_sizes, int n_in,
                              void* d_out, int out_size)
{
    const float* query = (const float*)d_in[0];
    const float* key   = (const float*)d_in[1];
    const float* value = (const float*)d_in[2];
    // d_in[3] = mask (int32 tril) — causal mask applied analytically in-kernel
    const float* w_q = (const float*)d_in[4];
    const float* b_q = (const float*)d_in[5];
    const float* w_k = (const float*)d_in[6];
    const float* b_k = (const float*)d_in[7];
    const float* w_v = (const float*)d_in[8];
    const float* b_v = (const float*)d_in[9];
    const float* w_o = (const float*)d_in[10];
    const float* b_o = (const float*)d_in[11];
    float* out = (float*)d_out;

    const int M  = in_sizes[0] / D_MODEL;   // B * S
    const int Bn = M / SEQ;

    float *q, *k, *v, *ctx;
    cudaGetSymbolAddress((void**)&q,   g_q);
    cudaGetSymbolAddress((void**)&k,   g_k);
    cudaGetSymbolAddress((void**)&v,   g_v);
    cudaGetSymbolAddress((void**)&ctx, g_ctx);

    cudaFuncSetAttribute(attn_mma_kernel,
                         cudaFuncAttributeMaxDynamicSharedMemorySize, ATTN_SMEM);

    dim3 ggrid(D_MODEL / 128, M / 128);
    gemm_mma_kernel<<<ggrid, 256>>>(query, w_q, b_q, q, M);
    gemm_mma_kernel<<<ggrid, 256>>>(key,   w_k, b_k, k, M);
    gemm_mma_kernel<<<ggrid, 256>>>(value, w_v, b_v, v, M);

    attn_mma_kernel<<<dim3(SEQ / AQ, NHEAD, Bn), 256, ATTN_SMEM>>>(q, k, v, ctx);

    gemm_mma_kernel<<<ggrid, 256>>>(ctx, w_o, b_o, out, M);
}

// round 6
// speedup vs baseline: 2.9162x; 1.0512x over previous
#include <cuda_runtime.h>
#include <cuda_bf16.h>
#include <cstdint>

#define D_MODEL 1024
#define NHEAD   16
#define DHEAD   64
#define SEQ     2048
#define MAXB    2

// Scratch (no device allocation allowed)
__device__ __nv_bfloat16 g_qh[MAXB * SEQ * D_MODEL];
__device__ __nv_bfloat16 g_ql[MAXB * SEQ * D_MODEL];
__device__ __nv_bfloat16 g_kh[MAXB * SEQ * D_MODEL];
__device__ __nv_bfloat16 g_kl[MAXB * SEQ * D_MODEL];
__device__ __nv_bfloat16 g_vh[MAXB * SEQ * D_MODEL];
__device__ __nv_bfloat16 g_vl[MAXB * SEQ * D_MODEL];
__device__ float g_ctx[MAXB * SEQ * D_MODEL];

// ===========================================================================
// Helpers
// ===========================================================================
__device__ __forceinline__ uint32_t smem_u32(const void* p) {
    uint32_t a;
    asm("{ .reg .u64 t; cvta.to.shared.u64 t, %1; cvt.u32.u64 %0, t; }"
        : "=r"(a) : "l"(p));
    return a;
}

__device__ __forceinline__ void ldsm4(uint32_t* r, uint32_t addr) {
    asm volatile("ldmatrix.sync.aligned.m8n8.x4.shared.b16 {%0,%1,%2,%3}, [%4];"
        : "=r"(r[0]), "=r"(r[1]), "=r"(r[2]), "=r"(r[3]) : "r"(addr));
}

__device__ __forceinline__ void ldsm4t(uint32_t* r, uint32_t addr) {
    asm volatile("ldmatrix.sync.aligned.m8n8.x4.trans.shared.b16 {%0,%1,%2,%3}, [%4];"
        : "=r"(r[0]), "=r"(r[1]), "=r"(r[2]), "=r"(r[3]) : "r"(addr));
}

__device__ __forceinline__ void mma16816(float* d, const uint32_t* a, const uint32_t* b) {
    asm volatile(
        "mma.sync.aligned.m16n8k16.row.col.f32.bf16.bf16.f32 "
        "{%0,%1,%2,%3}, {%4,%5,%6,%7}, {%8,%9}, {%0,%1,%2,%3};"
        : "+f"(d[0]), "+f"(d[1]), "+f"(d[2]), "+f"(d[3])
        : "r"(a[0]), "r"(a[1]), "r"(a[2]), "r"(a[3]), "r"(b[0]), "r"(b[1]));
}

__device__ __forceinline__ uint32_t pack_bf(float e, float o) {
    __nv_bfloat162 t = __floats2bfloat162_rn(e, o);
    return *reinterpret_cast<uint32_t*>(&t);
}

__device__ __forceinline__ void sts_v2(uint32_t addr, uint32_t v0, uint32_t v1) {
    asm volatile("st.shared.v2.b32 [%0], {%1,%2};" :: "r"(addr), "r"(v0), "r"(v1) : "memory");
}

__device__ __forceinline__ void split2(float a, float b, uint32_t& hi, uint32_t& lo) {
    hi = pack_bf(a, b);
    float ha = __uint_as_float(hi << 16);
    float hb = __uint_as_float(hi & 0xffff0000u);
    lo = pack_bf(a - ha, b - hb);
}

__device__ __forceinline__ void cpa16(uint32_t dst, const void* src) {
    asm volatile("cp.async.cg.shared.global [%0], [%1], 16;"
                 :: "r"(dst), "l"(src) : "memory");
}
#define CP_COMMIT() asm volatile("cp.async.commit_group;" ::: "memory")
#define CP_WAIT(n)  asm volatile("cp.async.wait_group %0;" :: "n"(n) : "memory")

// ===========================================================================
// GEMM body: Y[M,N] = X[M,K] @ W[N,K]^T + bias, fp32 via bf16 split (HH+HL+LH)
// CTA 128x128, 8 warps, BK=32.  SPLIT=true -> write hi/lo bf16 planes.
// ===========================================================================
#define GBK 32
#define GNCHUNK (D_MODEL / GBK)

template <bool SPLIT>
__device__ __forceinline__ void gemm_body(
    const float* __restrict__ X, const float* __restrict__ W,
    const float* __restrict__ bias, float* __restrict__ Y,
    __nv_bfloat16* __restrict__ Yh, __nv_bfloat16* __restrict__ Yl)
{
    __shared__ __align__(1024) uint8_t sA[128 * 128];
    __shared__ __align__(1024) uint8_t sB[128 * 128];
    const uint32_t sAu = smem_u32(sA);
    const uint32_t sBu = smem_u32(sB);

    const int tid  = threadIdx.x;
    const int wid  = tid >> 5;
    const int lane = tid & 31;
    const int m0 = blockIdx.y * 128;
    const int n0 = blockIdx.x * 128;
    const int wm = (wid >> 2) * 64;
    const int wn = (wid & 3) * 32;

    const int s_row = tid >> 3;
    const int s_c4  = tid & 7;
    const int s_g   = s_c4 >> 1;
    const int s_sub = (s_c4 & 1) * 8;

    float acc[4][4][4];
#pragma unroll
    for (int i = 0; i < 4; i++)
#pragma unroll
        for (int g = 0; g < 4; g++)
#pragma unroll
            for (int r = 0; r < 4; r++) acc[i][g][r] = 0.f;

    for (int c = 0; c < GNCHUNK; c++) {
        const int k0 = c * GBK;
        __syncthreads();
#pragma unroll
        for (int i = 0; i < 4; i++) {
            int row = s_row + i * 32;
            int r7 = row & 7;
            uint32_t offH = (uint32_t)(row * 128 + (((2 * s_g)     ^ r7) << 4) + s_sub);
            uint32_t offL = (uint32_t)(row * 128 + (((2 * s_g + 1) ^ r7) << 4) + s_sub);

            float4 a = *(const float4*)(X + (size_t)(m0 + row) * D_MODEL + k0 + s_c4 * 4);
            uint32_t h01, l01, h23, l23;
            split2(a.x, a.y, h01, l01);
            split2(a.z, a.w, h23, l23);
            sts_v2(sAu + offH, h01, h23);
            sts_v2(sAu + offL, l01, l23);

            float4 b = *(const float4*)(W + (size_t)(n0 + row) * D_MODEL + k0 + s_c4 * 4);
            split2(b.x, b.y, h01, l01);
            split2(b.z, b.w, h23, l23);
            sts_v2(sBu + offH, h01, h23);
            sts_v2(sBu + offL, l01, l23);
        }
        __syncthreads();

#pragma unroll
        for (int ks = 0; ks < 2; ks++) {
            uint32_t aH[4][4], aL[4][4], bH[4][2], bL[4][2];
            {
                int rA = wm + (lane & 15);
                int cHi = 4 * ks + 2 * ((lane >> 4) & 1);
                int r7 = rA & 7;
                uint32_t base = sAu + (uint32_t)rA * 128;
                uint32_t pH = (uint32_t)((cHi ^ r7) << 4);
                uint32_t pL = (uint32_t)(((cHi + 1) ^ r7) << 4);
#pragma unroll
                for (int i = 0; i < 4; i++) {
                    ldsm4(aH[i], base + i * 2048 + pH);
                    ldsm4(aL[i], base + i * 2048 + pL);
                }
            }
            {
                int rBb = wn + (lane & 7) + ((lane >> 4) & 1) * 8;
                int cHi = 4 * ks + 2 * ((lane >> 3) & 1);
#pragma unroll
                for (int j = 0; j < 2; j++) {
                    int rB = rBb + j * 16;
                    int r7 = rB & 7;
                    uint32_t base = sBu + (uint32_t)rB * 128;
                    uint32_t t[4];
                    ldsm4(t, base + (uint32_t)((cHi ^ r7) << 4));
                    bH[2 * j][0] = t[0]; bH[2 * j][1] = t[1];
                    bH[2 * j + 1][0] = t[2]; bH[2 * j + 1][1] = t[3];
                    ldsm4(t, base + (uint32_t)(((cHi + 1) ^ r7) << 4));
                    bL[2 * j][0] = t[0]; bL[2 * j][1] = t[1];
                    bL[2 * j + 1][0] = t[2]; bL[2 * j + 1][1] = t[3];
                }
            }
#pragma unroll
            for (int i = 0; i < 4; i++)
#pragma unroll
                for (int g = 0; g < 4; g++) {
                    mma16816(acc[i][g], aH[i], bH[g]);
                    mma16816(acc[i][g], aH[i], bL[g]);
                    mma16816(acc[i][g], aL[i], bH[g]);
                }
        }
    }

#pragma unroll
    for (int i = 0; i < 4; i++) {
        int row = m0 + wm + i * 16 + (lane >> 2);
#pragma unroll
        for (int g = 0; g < 4; g++) {
            int col = n0 + wn + g * 8 + (lane & 3) * 2;
            float2 b2 = *(const float2*)(bias + col);
            float v00 = acc[i][g][0] + b2.x, v01 = acc[i][g][1] + b2.y;
            float v10 = acc[i][g][2] + b2.x, v11 = acc[i][g][3] + b2.y;
            if (SPLIT) {
                uint32_t h, l;
                split2(v00, v01, h, l);
                *(uint32_t*)(Yh + (size_t)row * D_MODEL + col) = h;
                *(uint32_t*)(Yl + (size_t)row * D_MODEL + col) = l;
                split2(v10, v11, h, l);
                *(uint32_t*)(Yh + (size_t)(row + 8) * D_MODEL + col) = h;
                *(uint32_t*)(Yl + (size_t)(row + 8) * D_MODEL + col) = l;
            } else {
                float2 o0, o1;
                o0.x = v00; o0.y = v01;
                o1.x = v10; o1.y = v11;
                *(float2*)(Y + (size_t)row * D_MODEL + col) = o0;
                *(float2*)(Y + (size_t)(row + 8) * D_MODEL + col) = o1;
            }
        }
    }
}

// Fused Q/K/V projections: grid.z selects which
__global__ __launch_bounds__(256, 2) void gemm_qkv_kernel(
    const float* __restrict__ x0, const float* __restrict__ x1, const float* __restrict__ x2,
    const float* __restrict__ w0, const float* __restrict__ w1, const float* __restrict__ w2,
    const float* __restrict__ bi0, const float* __restrict__ bi1, const float* __restrict__ bi2,
    __nv_bfloat16* qh, __nv_bfloat16* ql, __nv_bfloat16* kh, __nv_bfloat16* kl,
    __nv_bfloat16* vh, __nv_bfloat16* vl)
{
    const int z = blockIdx.z;
    const float* X = (z == 0) ? x0 : (z == 1) ? x1 : x2;
    const float* W = (z == 0) ? w0 : (z == 1) ? w1 : w2;
    const float* B = (z == 0) ? bi0 : (z == 1) ? bi1 : bi2;
    __nv_bfloat16* Yh = (z == 0) ? qh : (z == 1) ? kh : vh;
    __nv_bfloat16* Yl = (z == 0) ? ql : (z == 1) ? kl : vl;
    gemm_body<true>(X, W, B, nullptr, Yh, Yl);
}

__global__ __launch_bounds__(256, 2) void gemm_out_kernel(
    const float* __restrict__ X, const float* __restrict__ W,
    const float* __restrict__ bias, float* __restrict__ Y)
{
    gemm_body<false>(X, W, bias, Y, nullptr, nullptr);
}

// ===========================================================================
// Flash attention (causal) on mma.sync bf16, pre-split inputs, cp.async
// double-buffered K/V.  CTA: 128 q-rows, 8 warps.
// SMEM: Qh 16K | Ql 16K | buf0 {Kh,Kl,Vh,Vl 8K each} | buf1 {same} = 96K
// ===========================================================================
#define AQ 128
#define AK 64
#define ATTN_SMEM 98304

__global__ __launch_bounds__(256) void attn_mma_kernel(
    const __nv_bfloat16* __restrict__ Qh, const __nv_bfloat16* __restrict__ Ql,
    const __nv_bfloat16* __restrict__ Kh, const __nv_bfloat16* __restrict__ Kl,
    const __nv_bfloat16* __restrict__ Vh, const __nv_bfloat16* __restrict__ Vl,
    float* __restrict__ Octx)
{
    extern __shared__ uint8_t dsm[];
    const uint32_t sQh = smem_u32(dsm);
    const uint32_t sQl = sQh + 16384;
    const uint32_t sBUF = sQh + 32768;     // + buf*32768: Kh,Kl,Vh,Vl (8K each)

    const int tid  = threadIdx.x;
    const int wid  = tid >> 5;
    const int lane = tid & 31;
    const int qt = blockIdx.x;
    const int h  = blockIdx.y;
    const int b  = blockIdx.z;
    const size_t gbase = ((size_t)b * SEQ) * D_MODEL + (size_t)h * DHEAD;

    const int nkt = 2 * qt + 2;

    // ---- prologue: stage Q (group with KV0), then KV1 ----
    {
        // Q: 2 planes x 1024 chunks(16B); 8 per thread
#pragma unroll
        for (int i = 0; i < 8; i++) {
            const int pl = i >> 2;                    // 0=hi,1=lo
            int c = (i & 3) * 256 + tid;              // 0..1023
            int row = c >> 3, c16 = c & 7;
            uint32_t dst = (pl ? sQl : sQh) + (uint32_t)(row * 128 + ((c16 ^ (row & 7)) << 4));
            const __nv_bfloat16* src = (pl ? Ql : Qh) + gbase + (size_t)(qt * AQ + row) * D_MODEL + c16 * 8;
            cpa16(dst, src);
        }
    }
    const __nv_bfloat16* kvsrc[4] = { Kh, Kl, Vh, Vl };
#pragma unroll
    for (int i = 0; i < 8; i++) {     // KV tile 0 -> buf0
        const int pl = i >> 1;
        int c = (i & 1) * 256 + tid;
        int row = c >> 3, c16 = c & 7;
        uint32_t dst = sBUF + pl * 8192 + (uint32_t)(row * 128 + ((c16 ^ (row & 7)) << 4));
        cpa16(dst, kvsrc[pl] + gbase + (size_t)row * D_MODEL + c16 * 8);
    }
    CP_COMMIT();
#pragma unroll
    for (int i = 0; i < 8; i++) {     // KV tile 1 -> buf1
        const int pl = i >> 1;
        int c = (i & 1) * 256 + tid;
        int row = c >> 3, c16 = c & 7;
        uint32_t dst = sBUF + 32768 + pl * 8192 + (uint32_t)(row * 128 + ((c16 ^ (row & 7)) << 4));
        cpa16(dst, kvsrc[pl] + gbase + (size_t)(AK + row) * D_MODEL + c16 * 8);
    }
    CP_COMMIT();

    uint32_t qfh[4][4], qfl[4][4];
    float O[8][4];
#pragma unroll
    for (int g = 0; g < 8; g++)
#pragma unroll
        for (int r = 0; r < 4; r++) O[g][r] = 0.f;
    float m0 = -1e30f, m1 = -1e30f, l0 = 0.f, l1 = 0.f;

    const int wrow0 = qt * AQ + wid * 16;
    const float scale = 0.125f;

    for (int jt = 0; jt < nkt; jt++) {
        if (jt + 1 < nkt) { CP_WAIT(1); } else { CP_WAIT(0); }
        __syncthreads();     // tile jt visible to all

        if (jt == 0) {       // persistent Q fragments
#pragma unroll
            for (int ks = 0; ks < 4; ks++) {
                int row = (wid << 4) + (lane & 15);
                int c16 = 2 * ks + (lane >> 4);
                uint32_t addr = (uint32_t)(row * 128 + ((c16 ^ (row & 7)) << 4));
                ldsm4(qfh[ks], sQh + addr);
                ldsm4(qfl[ks], sQl + addr);
            }
        }

        const uint32_t kb = sBUF + (uint32_t)(jt & 1) * 32768;
        const uint32_t sKh = kb, sKl = kb + 8192, sVh = kb + 16384, sVl = kb + 24576;

        if (wrow0 + 15 >= jt * AK) {
            // ---- S = Q @ K^T ----
            float S[8][4];
#pragma unroll
            for (int g = 0; g < 8; g++)
#pragma unroll
                for (int r = 0; r < 4; r++) S[g][r] = 0.f;

#pragma unroll
            for (int ks = 0; ks < 4; ks++) {
                uint32_t kh[4][4], kl[4][4];
#pragma unroll
                for (int g2 = 0; g2 < 4; g2++) {
                    int key = g2 * 16 + (lane & 7) + ((lane >> 4) & 1) * 8;
                    int c16 = 2 * ks + ((lane >> 3) & 1);
                    uint32_t addr = (uint32_t)(key * 128 + ((c16 ^ (key & 7)) << 4));
                    ldsm4(kh[g2], sKh + addr);
                    ldsm4(kl[g2], sKl + addr);
                }
#pragma unroll
                for (int g2 = 0; g2 < 4; g2++) {
                    mma16816(S[2 * g2],     qfh[ks], &kh[g2][0]);
                    mma16816(S[2 * g2],     qfh[ks], &kl[g2][0]);
                    mma16816(S[2 * g2],     qfl[ks], &kh[g2][0]);
                    mma16816(S[2 * g2 + 1], qfh[ks], &kh[g2][2]);
                    mma16816(S[2 * g2 + 1], qfh[ks], &kl[g2][2]);
                    mma16816(S[2 * g2 + 1], qfl[ks], &kh[g2][2]);
                }
            }

            // ---- scale + causal mask ----
            const int r0g = wrow0 + (lane >> 2);
            const bool domask = (jt * AK + 63) > wrow0;
            if (domask) {
                const int key0 = jt * AK + 2 * (lane & 3);
#pragma unroll
                for (int g = 0; g < 8; g++) {
                    int kk = key0 + 8 * g;
                    S[g][0] = (kk     <= r0g)     ? S[g][0] * scale : -1e30f;
                    S[g][1] = (kk + 1 <= r0g)     ? S[g][1] * scale : -1e30f;
                    S[g][2] = (kk     <= r0g + 8) ? S[g][2] * scale : -1e30f;
                    S[g][3] = (kk + 1 <= r0g + 8) ? S[g][3] * scale : -1e30f;
                }
            } else {
#pragma unroll
                for (int g = 0; g < 8; g++) {
                    S[g][0] *= scale; S[g][1] *= scale;
                    S[g][2] *= scale; S[g][3] *= scale;
                }
            }

            // ---- online softmax ----
            float mx0 = S[0][0], mx1 = S[0][2];
#pragma unroll
            for (int g = 0; g < 8; g++) {
                mx0 = fmaxf(mx0, fmaxf(S[g][0], S[g][1]));
                mx1 = fmaxf(mx1, fmaxf(S[g][2], S[g][3]));
            }
            mx0 = fmaxf(mx0, __shfl_xor_sync(0xffffffffu, mx0, 1));
            mx0 = fmaxf(mx0, __shfl_xor_sync(0xffffffffu, mx0, 2));
            mx1 = fmaxf(mx1, __shfl_xor_sync(0xffffffffu, mx1, 1));
            mx1 = fmaxf(mx1, __shfl_xor_sync(0xffffffffu, mx1, 2));
            float mn0 = fmaxf(m0, mx0), mn1 = fmaxf(m1, mx1);
            float corr0 = __expf(m0 - mn0), corr1 = __expf(m1 - mn1);
            m0 = mn0; m1 = mn1;

            float la0 = 0.f, la1 = 0.f;
            uint32_t ph[4][4], pl[4][4];
#pragma unroll
            for (int j = 0; j < 4; j++) {
                float p00 = __expf(S[2 * j][0] - mn0);
                float p01 = __expf(S[2 * j][1] - mn0);
                float p10 = __expf(S[2 * j][2] - mn1);
                float p11 = __expf(S[2 * j][3] - mn1);
                float p20 = __expf(S[2 * j + 1][0] - mn0);
                float p21 = __expf(S[2 * j + 1][1] - mn0);
                float p30 = __expf(S[2 * j + 1][2] - mn1);
                float p31 = __expf(S[2 * j + 1][3] - mn1);
                la0 += p00 + p01 + p20 + p21;
                la1 += p10 + p11 + p30 + p31;
                split2(p00, p01, ph[j][0], pl[j][0]);
                split2(p10, p11, ph[j][1], pl[j][1]);
                split2(p20, p21, ph[j][2], pl[j][2]);
                split2(p30, p31, ph[j][3], pl[j][3]);
            }
            l0 = l0 * corr0 + la0;
            l1 = l1 * corr1 + la1;
#pragma unroll
            for (int g = 0; g < 8; g++) {
                O[g][0] *= corr0; O[g][1] *= corr0;
                O[g][2] *= corr1; O[g][3] *= corr1;
            }

            // ---- O += P @ V ----
#pragma unroll
            for (int ks = 0; ks < 4; ks++) {
                uint32_t vh[4][4], vl[4][4];
#pragma unroll
                for (int d2 = 0; d2 < 4; d2++) {
                    int row = 16 * ks + (lane & 7) + ((lane >> 3) & 1) * 8;
                    int c16 = 2 * d2 + ((lane >> 4) & 1);
                    uint32_t addr = (uint32_t)(row * 128 + ((c16 ^ (row & 7)) << 4));
                    ldsm4t(vh[d2], sVh + addr);
                    ldsm4t(vl[d2], sVl + addr);
                }
#pragma unroll
                for (int d2 = 0; d2 < 4; d2++) {
                    mma16816(O[2 * d2],     ph[ks], &vh[d2][0]);
                    mma16816(O[2 * d2],     ph[ks], &vl[d2][0]);
                    mma16816(O[2 * d2],     pl[ks], &vh[d2][0]);
                    mma16816(O[2 * d2 + 1], ph[ks], &vh[d2][2]);
                    mma16816(O[2 * d2 + 1], ph[ks], &vl[d2][2]);
                    mma16816(O[2 * d2 + 1], pl[ks], &vh[d2][2]);
                }
            }
        }

        __syncthreads();   // all reads of buf[jt&1] done
        if (jt + 2 < nkt) {
#pragma unroll
            for (int i = 0; i < 8; i++) {
                const int pl2 = i >> 1;
                int c = (i & 1) * 256 + tid;
                int row = c >> 3, c16 = c & 7;
                uint32_t dst = sBUF + (uint32_t)(jt & 1) * 32768 + pl2 * 8192
                             + (uint32_t)(row * 128 + ((c16 ^ (row & 7)) << 4));
                cpa16(dst, kvsrc[pl2] + gbase + (size_t)((jt + 2) * AK + row) * D_MODEL + c16 * 8);
            }
            CP_COMMIT();
        }
    }

    // ---- epilogue ----
    l0 += __shfl_xor_sync(0xffffffffu, l0, 1);
    l0 += __shfl_xor_sync(0xffffffffu, l0, 2);
    l1 += __shfl_xor_sync(0xffffffffu, l1, 1);
    l1 += __shfl_xor_sync(0xffffffffu, l1, 2);
    float inv0 = 1.f / l0, inv1 = 1.f / l1;
    const int r0g = wrow0 + (lane >> 2);
#pragma unroll
    for (int g = 0; g < 8; g++) {
        int dim = 8 * g + 2 * (lane & 3);
        float2 o0, o1;
        o0.x = O[g][0] * inv0; o0.y = O[g][1] * inv0;
        o1.x = O[g][2] * inv1; o1.y = O[g][3] * inv1;
        *(float2*)(Octx + gbase + (size_t)r0g * D_MODEL + dim) = o0;
        *(float2*)(Octx + gbase + (size_t)(r0g + 8) * D_MODEL + dim) = o1;
    }
}

// ===========================================================================
extern "C" void kernel_launch(void* const* d_in, const int* in_sizes, int n_in,
                              void* d_out, int out_size)
{
    const float* query = (const float*)d_in[0];
    const float* key   = (const float*)d_in[1];
    const float* value = (const float*)d_in[2];
    // d_in[3] = mask — causal, applied analytically in-kernel
    const float* w_q = (const float*)d_in[4];
    const float* b_q = (const float*)d_in[5];
    const float* w_k = (const float*)d_in[6];
    const float* b_k = (const float*)d_in[7];
    const float* w_v = (const float*)d_in[8];
    const float* b_v = (const float*)d_in[9];
    const float* w_o = (const float*)d_in[10];
    const float* b_o = (const float*)d_in[11];
    float* out = (float*)d_out;

    const int M  = in_sizes[0] / D_MODEL;   // B * S
    const int Bn = M / SEQ;

    __nv_bfloat16 *qh, *ql, *kh, *kl, *vh, *vl;
    float* ctx;
    cudaGetSymbolAddress((void**)&qh, g_qh);
    cudaGetSymbolAddress((void**)&ql, g_ql);
    cudaGetSymbolAddress((void**)&kh, g_kh);
    cudaGetSymbolAddress((void**)&kl, g_kl);
    cudaGetSymbolAddress((void**)&vh, g_vh);
    cudaGetSymbolAddress((void**)&vl, g_vl);
    cudaGetSymbolAddress((void**)&ctx, g_ctx);

    cudaFuncSetAttribute(attn_mma_kernel,
                         cudaFuncAttributeMaxDynamicSharedMemorySize, ATTN_SMEM);

    dim3 qkvgrid(D_MODEL / 128, M / 128, 3);
    gemm_qkv_kernel<<<qkvgrid, 256>>>(query, key, value,
                                      w_q, w_k, w_v, b_q, b_k, b_v,
                                      qh, ql, kh, kl, vh, vl);

    attn_mma_kernel<<<dim3(SEQ / AQ, NHEAD, Bn), 256, ATTN_SMEM>>>(
        qh, ql, kh, kl, vh, vl, ctx);

    gemm_out_kernel<<<dim3(D_MODEL / 128, M / 128), 256>>>(ctx, w_o, b_o, out);
}